// round 1
// baseline (speedup 1.0000x reference)
#include <cuda_runtime.h>
#include <cuda_bf16.h>

// Flag: 1 if mul[a][b] == (a+b) % n for all entries (cyclic group in standard form).
__device__ int g_is_cyclic;

__global__ void check_cyclic_kernel(const int* __restrict__ mul, int n) {
    __shared__ int ok;
    if (threadIdx.x == 0) ok = 1;
    __syncthreads();
    int total = n * n;
    for (int i = threadIdx.x; i < total; i += blockDim.x) {
        int a = i / n;
        int b = i - a * n;
        int expect = a + b;
        if (expect >= n) expect -= n;
        if (__ldg(mul + i) != expect) ok = 0;  // benign race: all writers store 0
    }
    __syncthreads();
    if (threadIdx.x == 0) g_is_cyclic = ok;
}

// One warp per row. Fast path: sum mod n (cyclic). General path: ordered group
// product via Cayley-table lookups (per-lane contiguous chunk, then shfl_up scan).
__global__ void scan_rows_kernel(const float* __restrict__ scale_p,
                                 const int* __restrict__ ids,
                                 const int* __restrict__ mul,
                                 float* __restrict__ out,
                                 int n, int b_rows, int t_len) {
    int gwarp = (int)((blockIdx.x * blockDim.x + threadIdx.x) >> 5);
    int lane  = threadIdx.x & 31;
    if (gwarp >= b_rows) return;

    const int* row = ids + (long long)gwarp * t_len;
    int s;

    if (g_is_cyclic) {
        // --- Fast path: s = (sum of all ids in row) % n ---
        const int4* rowv = (const int4*)row;
        int nvec = t_len >> 2;               // 512 int4 per row
        int sum = 0;
        #pragma unroll 8
        for (int j = lane; j < nvec; j += 32) {
            int4 v = __ldg(rowv + j);        // coalesced 128B per warp step
            sum += v.x + v.y + v.z + v.w;
        }
        #pragma unroll
        for (int d = 16; d; d >>= 1)
            sum += __shfl_xor_sync(0xffffffffu, sum, d);
        s = sum % n;                          // max sum 2048*59 fits easily in int
    } else {
        // --- General path: associative group product, order-preserving ---
        // Row product P = x_{T-1} . x_{T-2} . ... . x_0  (applied to identity 0).
        int chunk = t_len >> 5;               // elements per lane, time-contiguous
        const int* base = row + lane * chunk;
        int q = 0;                            // ID_ID = 0 is the identity element
        for (int j = 0; j < chunk; j++) {
            int x = __ldg(base + j);
            q = __ldg(mul + x * n + q);       // q = x . q
        }
        // Ordered inclusive scan across lanes: q_l = Q_l . Q_{l-1} . ... . Q_0
        #pragma unroll
        for (int d = 1; d < 32; d <<= 1) {
            int t = __shfl_up_sync(0xffffffffu, q, d);
            if (lane >= d) q = __ldg(mul + q * n + t);
        }
        s = __shfl_sync(0xffffffffu, q, 31);
    }

    float sc = __ldg(scale_p);
    float hi = 10.0f * sc;
    float lo = -10.0f * sc;
    float* orow = out + (long long)gwarp * n;
    for (int i = lane; i < n; i += 32)
        orow[i] = (i == s) ? hi : lo;
}

extern "C" void kernel_launch(void* const* d_in, const int* in_sizes, int n_in,
                              void* d_out, int out_size) {
    const float* scale = (const float*)d_in[0];
    const int*   ids   = (const int*)d_in[1];
    const int*   mul   = (const int*)d_in[2];
    float*       out   = (float*)d_out;

    // n from the Cayley table size (n*n elements)
    int mn = in_sizes[2];
    int n = 1;
    while (n * n < mn) n++;

    int b_rows = out_size / n;                 // 8192
    int t_len  = in_sizes[1] / b_rows;         // 2048

    check_cyclic_kernel<<<1, 256>>>(mul, n);

    const int warps_per_block = 8;             // 256 threads
    int blocks = (b_rows + warps_per_block - 1) / warps_per_block;
    scan_rows_kernel<<<blocks, warps_per_block * 32>>>(scale, ids, mul, out,
                                                       n, b_rows, t_len);
}

// round 2
// speedup vs baseline: 1.0113x; 1.0113x over previous
#include <cuda_runtime.h>
#include <cuda_bf16.h>

// Single fused kernel:
//  - each warp owns one row of input_ids [t_len]
//  - 8-deep explicit int4 load batches (forces MLP=8 in SASS)
//  - block-cooperative Cayley-table check (cyclic Z_n?) overlapped with the
//    first load batch; fast path = sum mod n, fallback = ordered group product.

#define TPB 256  // 8 warps/block

__global__ void __launch_bounds__(TPB) a5_scan_fused_kernel(
    const float* __restrict__ scale_p,
    const int* __restrict__ ids,
    const int* __restrict__ mul,
    float* __restrict__ out,
    int n, int b_rows, int t_len)
{
    __shared__ int s_ok;
    int tid  = threadIdx.x;
    int lane = tid & 31;
    int gwarp = (int)((blockIdx.x * (unsigned)TPB + tid) >> 5);
    bool active = (gwarp < b_rows);

    int nvec = t_len >> 2;
    bool vec_ok = ((t_len & 3) == 0);
    const int4* rowv = nullptr;
    if (active && vec_ok)
        rowv = (const int4*)(ids + (long long)gwarp * t_len);

    // ---- Batch 0: issue 8 independent LDG.128 immediately (MLP=8) ----
    int4 v[8];
    bool have_b0 = active && vec_ok && (nvec >= 256);
    if (have_b0) {
        #pragma unroll
        for (int u = 0; u < 8; u++)
            v[u] = __ldg(rowv + lane + u * 32);
    }

    // ---- Overlapped table check: mul[a][b] == (a+b) % n ? ----
    if (tid == 0) s_ok = 1;
    __syncthreads();
    {
        int total = n * n;
        for (int i = tid; i < total; i += TPB) {
            int a = i / n;
            int b = i - a * n;
            int e = a + b;
            if (e >= n) e -= n;
            if (__ldg(mul + i) != e) s_ok = 0;   // benign race, all write 0
        }
    }
    __syncthreads();
    bool cyclic = (s_ok != 0);

    if (!active) return;

    int s;
    if (cyclic && vec_ok) {
        // ---- Fast path: s = (sum of row) % n ----
        int sum = 0;
        int j = lane;
        if (have_b0) {
            #pragma unroll
            for (int u = 0; u < 8; u++)
                sum += v[u].x + v[u].y + v[u].z + v[u].w;
            j += 256;
        }
        // Remaining full 8-deep batches
        for (; j + 7 * 32 < nvec; j += 256) {
            int4 w[8];
            #pragma unroll
            for (int u = 0; u < 8; u++)
                w[u] = __ldg(rowv + j + u * 32);
            #pragma unroll
            for (int u = 0; u < 8; u++)
                sum += w[u].x + w[u].y + w[u].z + w[u].w;
        }
        // Remainder vectors
        for (; j < nvec; j += 32) {
            int4 w = __ldg(rowv + j);
            sum += w.x + w.y + w.z + w.w;
        }
        #pragma unroll
        for (int d = 16; d; d >>= 1)
            sum += __shfl_xor_sync(0xffffffffu, sum, d);
        s = sum % n;
    } else {
        // ---- General path: ordered group product (correctness fallback) ----
        const int* row = ids + (long long)gwarp * t_len;
        if ((t_len & 31) == 0) {
            int chunk = t_len >> 5;
            const int* base = row + lane * chunk;
            int q = 0;  // identity
            for (int j = 0; j < chunk; j++) {
                int x = __ldg(base + j);
                q = __ldg(mul + x * n + q);     // q = x . q
            }
            #pragma unroll
            for (int d = 1; d < 32; d <<= 1) {
                int t = __shfl_up_sync(0xffffffffu, q, d);
                if (lane >= d) q = __ldg(mul + q * n + t);
            }
            s = __shfl_sync(0xffffffffu, q, 31);
        } else {
            int q = 0;
            if (lane == 0)
                for (int j = 0; j < t_len; j++)
                    q = __ldg(mul + __ldg(row + j) * n + q);
            s = __shfl_sync(0xffffffffu, q, 0);
        }
    }

    float sc = __ldg(scale_p);
    float hi = 10.0f * sc;
    float lo = -10.0f * sc;
    float* orow = out + (long long)gwarp * n;
    for (int i = lane; i < n; i += 32)
        orow[i] = (i == s) ? hi : lo;
}

extern "C" void kernel_launch(void* const* d_in, const int* in_sizes, int n_in,
                              void* d_out, int out_size) {
    const float* scale = (const float*)d_in[0];
    const int*   ids   = (const int*)d_in[1];
    const int*   mul   = (const int*)d_in[2];
    float*       out   = (float*)d_out;

    int mn = in_sizes[2];
    int n = 1;
    while (n * n < mn) n++;

    int b_rows = out_size / n;              // 8192
    int t_len  = in_sizes[1] / b_rows;      // 2048

    int warps_per_block = TPB / 32;
    int blocks = (b_rows + warps_per_block - 1) / warps_per_block;
    a5_scan_fused_kernel<<<blocks, TPB>>>(scale, ids, mul, out,
                                          n, b_rows, t_len);
}